// round 2
// baseline (speedup 1.0000x reference)
#include <cuda_runtime.h>
#include <math.h>

#define H 4096
#define EPS 1e-5f
#define ROWS_PER_BLOCK 8
#define NBLOCKS (5 * H / ROWS_PER_BLOCK)   // 2560

// Scratch for z = W @ x (5H floats) + completion counter.
__device__ float g_z[5 * H];
__device__ unsigned int g_count = 0;

__device__ __forceinline__ float sigmoidf_(float x) {
    return 1.0f / (1.0f + __expf(-x));
}

// ---------------------------------------------------------------------------
// Fused kernel:
//   Phase 1 (all 2560 blocks): GEMV  z[r] = dot(W[r], [h0;h1]), 1 warp/row.
//   Phase 2 (last block only): full LSTM-cell epilogue with 256 threads.
// ---------------------------------------------------------------------------
__global__ __launch_bounds__(256, 4)
void fused_kernel(const float* __restrict__ h0,
                  const float* __restrict__ h1,
                  const float* __restrict__ W,
                  const float* __restrict__ c0,
                  const float* __restrict__ c1,
                  const float* __restrict__ ffio_g,
                  const float* __restrict__ ffio_b,
                  const float* __restrict__ u_g,
                  const float* __restrict__ u_b,
                  const float* __restrict__ c_g,
                  const float* __restrict__ c_b,
                  float* __restrict__ out)
{
    __shared__ float xs[2 * H];          // 32 KB: x in phase 1, {cell, o} in phase 2
    __shared__ float red_s[6][8];
    __shared__ float red_q[6][8];
    __shared__ float stat_mean[6];
    __shared__ float stat_rstd[6];
    __shared__ bool  is_last;

    const int tid  = threadIdx.x;
    const int warp = tid >> 5;
    const int lane = tid & 31;

    // ---- Phase 1: GEMV -----------------------------------------------------
    {
        const float4* h0v = reinterpret_cast<const float4*>(h0);
        const float4* h1v = reinterpret_cast<const float4*>(h1);
        float4* xsv = reinterpret_cast<float4*>(xs);
        #pragma unroll
        for (int i = tid; i < H / 4; i += 256) {
            xsv[i]         = h0v[i];
            xsv[i + H / 4] = h1v[i];
        }
        __syncthreads();

        const int row = blockIdx.x * ROWS_PER_BLOCK + warp;
        const float4* wrow = reinterpret_cast<const float4*>(W + (size_t)row * (2 * H));

        float a0 = 0.f, a1 = 0.f, a2 = 0.f, a3 = 0.f;
        #pragma unroll 8
        for (int i = lane; i < (2 * H) / 4; i += 32) {
            float4 w = wrow[i];
            float4 x = xsv[i];
            a0 = fmaf(w.x, x.x, a0);
            a1 = fmaf(w.y, x.y, a1);
            a2 = fmaf(w.z, x.z, a2);
            a3 = fmaf(w.w, x.w, a3);
        }
        float s = (a0 + a1) + (a2 + a3);
        #pragma unroll
        for (int off = 16; off > 0; off >>= 1)
            s += __shfl_down_sync(0xffffffffu, s, off);
        if (lane == 0) g_z[row] = s;
    }

    // ---- Completion handshake ----------------------------------------------
    __threadfence();
    __syncthreads();
    if (tid == 0) {
        unsigned int prev = atomicAdd(&g_count, 1u);
        is_last = (prev == NBLOCKS - 1);
        if (is_last) g_count = 0;   // reset for next graph replay
    }
    __syncthreads();
    if (!is_last) return;
    __threadfence();                // make other blocks' g_z writes visible

    // ---- Phase 2: epilogue (256 threads) ------------------------------------
    // Thread t owns float4 indices { t + 256*j : j=0..3 } of each 4096-vector.
    const float4* gz4 = reinterpret_cast<const float4*>(g_z);
    float* scell = xs;              // 4096 floats
    float* so    = xs + H;          // 4096 floats

    // Pass A: sums / sumsq for the 5 z-parts
    float s5[5] = {0,0,0,0,0};
    float q5[5] = {0,0,0,0,0};
    #pragma unroll
    for (int j = 0; j < 4; j++) {
        const int idx = tid + 256 * j;
        #pragma unroll
        for (int p = 0; p < 5; p++) {
            float4 v = gz4[p * (H / 4) + idx];
            s5[p] += (v.x + v.y) + (v.z + v.w);
            q5[p] = fmaf(v.x, v.x, fmaf(v.y, v.y, fmaf(v.z, v.z, fmaf(v.w, v.w, q5[p]))));
        }
    }
    #pragma unroll
    for (int p = 0; p < 5; p++) {
        float s = s5[p], q = q5[p];
        #pragma unroll
        for (int off = 16; off > 0; off >>= 1) {
            s += __shfl_down_sync(0xffffffffu, s, off);
            q += __shfl_down_sync(0xffffffffu, q, off);
        }
        if (lane == 0) { red_s[p][warp] = s; red_q[p][warp] = q; }
    }
    __syncthreads();
    if (tid < 5) {
        float s = 0.f, q = 0.f;
        #pragma unroll
        for (int w = 0; w < 8; w++) { s += red_s[tid][w]; q += red_q[tid][w]; }
        float mean = s * (1.0f / H);
        float var  = q * (1.0f / H) - mean * mean;
        stat_mean[tid] = mean;
        stat_rstd[tid] = rsqrtf(var + EPS);
    }
    __syncthreads();

    // Pass B: gates, u, cell; stash cell & o in shared; reduce cell stats
    float cs = 0.f, cq = 0.f;
    #pragma unroll
    for (int j = 0; j < 4; j++) {
        const int idx = tid + 256 * j;

        float g4[4][4];   // f0, f1, i, o after sigmoid(LN)
        #pragma unroll
        for (int p = 0; p < 4; p++) {
            float4 v  = gz4[p * (H / 4) + idx];
            float4 gv = reinterpret_cast<const float4*>(ffio_g + p * H)[idx];
            float4 bv = reinterpret_cast<const float4*>(ffio_b + p * H)[idx];
            float m = stat_mean[p], r = stat_rstd[p];
            g4[p][0] = sigmoidf_(fmaf((v.x - m) * r, gv.x, bv.x));
            g4[p][1] = sigmoidf_(fmaf((v.y - m) * r, gv.y, bv.y));
            g4[p][2] = sigmoidf_(fmaf((v.z - m) * r, gv.z, bv.z));
            g4[p][3] = sigmoidf_(fmaf((v.w - m) * r, gv.w, bv.w));
        }

        float uv[4];
        {
            float4 v  = gz4[4 * (H / 4) + idx];
            float4 gv = reinterpret_cast<const float4*>(u_g)[idx];
            float4 bv = reinterpret_cast<const float4*>(u_b)[idx];
            float m = stat_mean[4], r = stat_rstd[4];
            uv[0] = tanhf(fmaf((v.x - m) * r, gv.x, bv.x));
            uv[1] = tanhf(fmaf((v.y - m) * r, gv.y, bv.y));
            uv[2] = tanhf(fmaf((v.z - m) * r, gv.z, bv.z));
            uv[3] = tanhf(fmaf((v.w - m) * r, gv.w, bv.w));
        }

        float4 c0v = reinterpret_cast<const float4*>(c0)[idx];
        float4 c1v = reinterpret_cast<const float4*>(c1)[idx];
        float c0a[4] = {c0v.x, c0v.y, c0v.z, c0v.w};
        float c1a[4] = {c1v.x, c1v.y, c1v.z, c1v.w};

        #pragma unroll
        for (int k = 0; k < 4; k++) {
            float cell = fmaf(g4[2][k], uv[k],
                         fmaf(g4[0][k], c0a[k], g4[1][k] * c1a[k]));
            scell[idx * 4 + k] = cell;
            so[idx * 4 + k]    = g4[3][k];
            cs += cell;
            cq  = fmaf(cell, cell, cq);
        }
    }
    {
        float s = cs, q = cq;
        #pragma unroll
        for (int off = 16; off > 0; off >>= 1) {
            s += __shfl_down_sync(0xffffffffu, s, off);
            q += __shfl_down_sync(0xffffffffu, q, off);
        }
        if (lane == 0) { red_s[5][warp] = s; red_q[5][warp] = q; }
    }
    __syncthreads();
    if (tid == 0) {
        float s = 0.f, q = 0.f;
        #pragma unroll
        for (int w = 0; w < 8; w++) { s += red_s[5][w]; q += red_q[5][w]; }
        float mean = s * (1.0f / H);
        float var  = q * (1.0f / H) - mean * mean;
        stat_mean[5] = mean;
        stat_rstd[5] = rsqrtf(var + EPS);
    }
    __syncthreads();

    // Pass C: final LN on cell, outputs
    const float m = stat_mean[5], r = stat_rstd[5];
    #pragma unroll
    for (int j = 0; j < 4; j++) {
        const int idx = tid + 256 * j;
        float4 cgv = reinterpret_cast<const float4*>(c_g)[idx];
        float4 cbv = reinterpret_cast<const float4*>(c_b)[idx];
        float cga[4] = {cgv.x, cgv.y, cgv.z, cgv.w};
        float cba[4] = {cbv.x, cbv.y, cbv.z, cbv.w};

        float4 hid, ncl;
        float nc[4], hd[4];
        #pragma unroll
        for (int k = 0; k < 4; k++) {
            float cell = scell[idx * 4 + k];
            nc[k] = fmaf((cell - m) * r, cga[k], cba[k]);
            hd[k] = so[idx * 4 + k] * tanhf(nc[k]);
        }
        hid.x = hd[0]; hid.y = hd[1]; hid.z = hd[2]; hid.w = hd[3];
        ncl.x = nc[0]; ncl.y = nc[1]; ncl.z = nc[2]; ncl.w = nc[3];

        reinterpret_cast<float4*>(out)[idx]     = hid;   // new_hidden
        reinterpret_cast<float4*>(out + H)[idx] = ncl;   // new_cell
    }
}

// ---------------------------------------------------------------------------
// Inputs (metadata order): 0=h0, 1=c0, 2=h1, 3=c1, 4=W,
//   5=ffio_g(4H), 6=ffio_b(4H), 7=u_g, 8=u_b, 9=c_g, 10=c_b
// Output: [new_hidden(4096); new_cell(4096)] fp32
// ---------------------------------------------------------------------------
extern "C" void kernel_launch(void* const* d_in, const int* in_sizes, int n_in,
                              void* d_out, int out_size)
{
    const float* h0     = (const float*)d_in[0];
    const float* c0     = (const float*)d_in[1];
    const float* h1     = (const float*)d_in[2];
    const float* c1     = (const float*)d_in[3];
    const float* W      = (const float*)d_in[4];
    const float* ffio_g = (const float*)d_in[5];
    const float* ffio_b = (const float*)d_in[6];
    const float* u_g    = (const float*)d_in[7];
    const float* u_b    = (const float*)d_in[8];
    const float* c_g    = (const float*)d_in[9];
    const float* c_b    = (const float*)d_in[10];
    float* out = (float*)d_out;

    fused_kernel<<<NBLOCKS, 256>>>(h0, h1, W, c0, c1,
                                   ffio_g, ffio_b, u_g, u_b, c_g, c_b, out);
}

// round 3
// speedup vs baseline: 1.1285x; 1.1285x over previous
#include <cuda_runtime.h>
#include <cooperative_groups.h>
#include <math.h>

namespace cg = cooperative_groups;

#define H 4096
#define EPS 1e-5f
#define ROWS_PER_BLOCK 8
#define ECTAS 4
#define ETHREADS 256

// Scratch for z = W @ x (5H floats).
__device__ float g_z[5 * H];

__device__ __forceinline__ float sigmoidf_(float x) {
    return 1.0f / (1.0f + __expf(-x));
}

// ---------------------------------------------------------------------------
// Kernel 1: GEMV  z[r] = dot(W[r, 0:2H], x)  where x = concat(h0, h1)
// One warp per output row; x staged in shared memory once per block.
// (UNCHANGED from the 110.8us round-1 version — measured at ~6.75 TB/s.)
// ---------------------------------------------------------------------------
__global__ __launch_bounds__(256, 4)
void gemv_kernel(const float* __restrict__ h0,
                 const float* __restrict__ h1,
                 const float* __restrict__ W)
{
    __shared__ float xs[2 * H];

    const int tid = threadIdx.x;

    const float4* h0v = reinterpret_cast<const float4*>(h0);
    const float4* h1v = reinterpret_cast<const float4*>(h1);
    float4* xsv = reinterpret_cast<float4*>(xs);
    #pragma unroll
    for (int i = tid; i < H / 4; i += 256) {
        xsv[i]         = h0v[i];
        xsv[i + H / 4] = h1v[i];
    }
    __syncthreads();

    const int warp = tid >> 5;
    const int lane = tid & 31;
    const int row  = blockIdx.x * ROWS_PER_BLOCK + warp;

    const float4* wrow = reinterpret_cast<const float4*>(W + (size_t)row * (2 * H));

    float a0 = 0.f, a1 = 0.f, a2 = 0.f, a3 = 0.f;
    #pragma unroll 8
    for (int i = lane; i < (2 * H) / 4; i += 32) {
        float4 w = wrow[i];
        float4 x = xsv[i];
        a0 = fmaf(w.x, x.x, a0);
        a1 = fmaf(w.y, x.y, a1);
        a2 = fmaf(w.z, x.z, a2);
        a3 = fmaf(w.w, x.w, a3);
    }
    float s = (a0 + a1) + (a2 + a3);
    #pragma unroll
    for (int off = 16; off > 0; off >>= 1)
        s += __shfl_down_sync(0xffffffffu, s, off);

    if (lane == 0) g_z[row] = s;
}

// ---------------------------------------------------------------------------
// Kernel 2: clustered epilogue. 4 CTAs x 256 threads, one cluster.
// CTA r owns float4 indices [r*256, (r+1)*256) of every 4096-wide vector
// (thread t -> global float4 index g = r*256 + t).
// Cross-CTA LayerNorm reductions via DSMEM partials + cluster.sync().
// ---------------------------------------------------------------------------
__global__ __launch_bounds__(ETHREADS, 1) __cluster_dims__(ECTAS, 1, 1)
void epilogue_kernel(const float* __restrict__ c0,
                     const float* __restrict__ c1,
                     const float* __restrict__ ffio_g,
                     const float* __restrict__ ffio_b,
                     const float* __restrict__ u_g,
                     const float* __restrict__ u_b,
                     const float* __restrict__ c_g,
                     const float* __restrict__ c_b,
                     float* __restrict__ out)
{
    cg::cluster_group cluster = cg::this_cluster();
    const unsigned rank = cluster.block_rank();

    __shared__ float ps[6][ECTAS];      // per-part CTA partial sums (peer-written)
    __shared__ float pq[6][ECTAS];      // per-part CTA partial sumsq
    __shared__ float wp_s[6][8];        // per-warp partials within CTA
    __shared__ float wp_q[6][8];
    __shared__ float stat_m[6];
    __shared__ float stat_r[6];

    const int t    = threadIdx.x;
    const int warp = t >> 5;
    const int lane = t & 31;
    const int g    = (int)rank * ETHREADS + t;   // float4 index 0..1023

    const float4* gz4 = reinterpret_cast<const float4*>(g_z);

    // ---- Pass A: load z parts, per-part reductions --------------------------
    float v[5][4];
    #pragma unroll
    for (int p = 0; p < 5; p++) {
        float4 vv = gz4[p * (H / 4) + g];
        v[p][0] = vv.x; v[p][1] = vv.y; v[p][2] = vv.z; v[p][3] = vv.w;
    }

    #pragma unroll
    for (int p = 0; p < 5; p++) {
        float s = (v[p][0] + v[p][1]) + (v[p][2] + v[p][3]);
        float q = fmaf(v[p][0], v[p][0], fmaf(v[p][1], v[p][1],
                  fmaf(v[p][2], v[p][2], v[p][3] * v[p][3])));
        #pragma unroll
        for (int off = 16; off > 0; off >>= 1) {
            s += __shfl_down_sync(0xffffffffu, s, off);
            q += __shfl_down_sync(0xffffffffu, q, off);
        }
        if (lane == 0) { wp_s[p][warp] = s; wp_q[p][warp] = q; }
    }
    __syncthreads();

    // Threads 0..4: finalize CTA partial for part p=t, publish to all peers.
    if (t < 5) {
        float s = 0.f, q = 0.f;
        #pragma unroll
        for (int w = 0; w < 8; w++) { s += wp_s[t][w]; q += wp_q[t][w]; }
        #pragma unroll
        for (int peer = 0; peer < ECTAS; peer++) {
            float* rs = cluster.map_shared_rank(&ps[0][0], peer);
            float* rq = cluster.map_shared_rank(&pq[0][0], peer);
            rs[t * ECTAS + rank] = s;
            rq[t * ECTAS + rank] = q;
        }
    }
    cluster.sync();

    if (t < 5) {
        float s = 0.f, q = 0.f;
        #pragma unroll
        for (int c = 0; c < ECTAS; c++) { s += ps[t][c]; q += pq[t][c]; }
        float mean = s * (1.0f / H);
        float var  = q * (1.0f / H) - mean * mean;
        stat_m[t] = mean;
        stat_r[t] = rsqrtf(var + EPS);
    }
    __syncthreads();

    // ---- Pass B: gates, u, cell; reduce cell stats ---------------------------
    float gate[4][4];
    #pragma unroll
    for (int p = 0; p < 4; p++) {
        float4 gv = reinterpret_cast<const float4*>(ffio_g + p * H)[g];
        float4 bv = reinterpret_cast<const float4*>(ffio_b + p * H)[g];
        float ga[4] = {gv.x, gv.y, gv.z, gv.w};
        float ba[4] = {bv.x, bv.y, bv.z, bv.w};
        float m = stat_m[p], r = stat_r[p];
        #pragma unroll
        for (int k = 0; k < 4; k++)
            gate[p][k] = sigmoidf_(fmaf((v[p][k] - m) * r, ga[k], ba[k]));
    }

    float uval[4];
    {
        float4 gv = reinterpret_cast<const float4*>(u_g)[g];
        float4 bv = reinterpret_cast<const float4*>(u_b)[g];
        float m = stat_m[4], r = stat_r[4];
        uval[0] = tanhf(fmaf((v[4][0] - m) * r, gv.x, bv.x));
        uval[1] = tanhf(fmaf((v[4][1] - m) * r, gv.y, bv.y));
        uval[2] = tanhf(fmaf((v[4][2] - m) * r, gv.z, bv.z));
        uval[3] = tanhf(fmaf((v[4][3] - m) * r, gv.w, bv.w));
    }

    float4 c0v = reinterpret_cast<const float4*>(c0)[g];
    float4 c1v = reinterpret_cast<const float4*>(c1)[g];
    float c0a[4] = {c0v.x, c0v.y, c0v.z, c0v.w};
    float c1a[4] = {c1v.x, c1v.y, c1v.z, c1v.w};

    float cell[4];
    #pragma unroll
    for (int k = 0; k < 4; k++)
        cell[k] = fmaf(gate[2][k], uval[k],
                  fmaf(gate[0][k], c0a[k], gate[1][k] * c1a[k]));

    {
        float s = (cell[0] + cell[1]) + (cell[2] + cell[3]);
        float q = fmaf(cell[0], cell[0], fmaf(cell[1], cell[1],
                  fmaf(cell[2], cell[2], cell[3] * cell[3])));
        #pragma unroll
        for (int off = 16; off > 0; off >>= 1) {
            s += __shfl_down_sync(0xffffffffu, s, off);
            q += __shfl_down_sync(0xffffffffu, q, off);
        }
        if (lane == 0) { wp_s[5][warp] = s; wp_q[5][warp] = q; }
    }
    __syncthreads();

    if (t == 0) {
        float s = 0.f, q = 0.f;
        #pragma unroll
        for (int w = 0; w < 8; w++) { s += wp_s[5][w]; q += wp_q[5][w]; }
        #pragma unroll
        for (int peer = 0; peer < ECTAS; peer++) {
            float* rs = cluster.map_shared_rank(&ps[0][0], peer);
            float* rq = cluster.map_shared_rank(&pq[0][0], peer);
            rs[5 * ECTAS + rank] = s;
            rq[5 * ECTAS + rank] = q;
        }
    }
    cluster.sync();

    if (t == 0) {
        float s = 0.f, q = 0.f;
        #pragma unroll
        for (int c = 0; c < ECTAS; c++) { s += ps[5][c]; q += pq[5][c]; }
        float mean = s * (1.0f / H);
        float var  = q * (1.0f / H) - mean * mean;
        stat_m[5] = mean;
        stat_r[5] = rsqrtf(var + EPS);
    }
    __syncthreads();

    // ---- Pass C: final LN + outputs ------------------------------------------
    const float m = stat_m[5], r = stat_r[5];
    float4 cgv = reinterpret_cast<const float4*>(c_g)[g];
    float4 cbv = reinterpret_cast<const float4*>(c_b)[g];
    float cga[4] = {cgv.x, cgv.y, cgv.z, cgv.w};
    float cba[4] = {cbv.x, cbv.y, cbv.z, cbv.w};

    float4 hid, ncl;
    float nc[4], hd[4];
    #pragma unroll
    for (int k = 0; k < 4; k++) {
        nc[k] = fmaf((cell[k] - m) * r, cga[k], cba[k]);
        hd[k] = gate[3][k] * tanhf(nc[k]);
    }
    hid.x = hd[0]; hid.y = hd[1]; hid.z = hd[2]; hid.w = hd[3];
    ncl.x = nc[0]; ncl.y = nc[1]; ncl.z = nc[2]; ncl.w = nc[3];

    reinterpret_cast<float4*>(out)[g]     = hid;   // new_hidden
    reinterpret_cast<float4*>(out + H)[g] = ncl;   // new_cell
}

// ---------------------------------------------------------------------------
// Inputs (metadata order): 0=h0, 1=c0, 2=h1, 3=c1, 4=W,
//   5=ffio_g(4H), 6=ffio_b(4H), 7=u_g, 8=u_b, 9=c_g, 10=c_b
// Output: [new_hidden(4096); new_cell(4096)] fp32
// ---------------------------------------------------------------------------
extern "C" void kernel_launch(void* const* d_in, const int* in_sizes, int n_in,
                              void* d_out, int out_size)
{
    const float* h0     = (const float*)d_in[0];
    const float* c0     = (const float*)d_in[1];
    const float* h1     = (const float*)d_in[2];
    const float* c1     = (const float*)d_in[3];
    const float* W      = (const float*)d_in[4];
    const float* ffio_g = (const float*)d_in[5];
    const float* ffio_b = (const float*)d_in[6];
    const float* u_g    = (const float*)d_in[7];
    const float* u_b    = (const float*)d_in[8];
    const float* c_g    = (const float*)d_in[9];
    const float* c_b    = (const float*)d_in[10];
    float* out = (float*)d_out;

    const int rows = 5 * H;                       // 20480
    gemv_kernel<<<rows / ROWS_PER_BLOCK, 256>>>(h0, h1, W);
    epilogue_kernel<<<ECTAS, ETHREADS>>>(c0, c1, ffio_g, ffio_b,
                                         u_g, u_b, c_g, c_b, out);
}

// round 4
// speedup vs baseline: 1.1315x; 1.0026x over previous
#include <cuda_runtime.h>
#include <math.h>

#define H 4096
#define EPS 1e-5f
#define ROWS_PER_BLOCK 8
#define NBLOCKS (5 * H / ROWS_PER_BLOCK)   // 2560, 512 blocks per z-part

// Scratch for z = W @ x (5H floats) + per-part stat accumulators.
__device__ float g_z[5 * H];
__device__ float g_sum[5]   = {0.f, 0.f, 0.f, 0.f, 0.f};
__device__ float g_sumsq[5] = {0.f, 0.f, 0.f, 0.f, 0.f};

__device__ __forceinline__ float sigmoidf_(float x) {
    return 1.0f / (1.0f + __expf(-x));
}
// tanh(x) = 1 - 2/(exp(2x)+1); exp overflow -> inf -> 1, underflow -> 0 -> -1.
__device__ __forceinline__ float tanhf_(float x) {
    return 1.0f - 2.0f / (__expf(2.0f * x) + 1.0f);
}

// ---------------------------------------------------------------------------
// Kernel 1: GEMV  z[r] = dot(W[r, 0:2H], [h0;h1]) ; one warp per row.
// Also accumulates per-part (sum, sumsq) of z via 2 block-level atomicAdds.
// ---------------------------------------------------------------------------
__global__ __launch_bounds__(256, 4)
void gemv_kernel(const float* __restrict__ h0,
                 const float* __restrict__ h1,
                 const float* __restrict__ W)
{
    __shared__ float xs[2 * H];
    __shared__ float rs[8], rq[8];

    const int tid = threadIdx.x;

    const float4* h0v = reinterpret_cast<const float4*>(h0);
    const float4* h1v = reinterpret_cast<const float4*>(h1);
    float4* xsv = reinterpret_cast<float4*>(xs);
    #pragma unroll
    for (int i = tid; i < H / 4; i += 256) {
        xsv[i]         = h0v[i];
        xsv[i + H / 4] = h1v[i];
    }
    __syncthreads();

    const int warp = tid >> 5;
    const int lane = tid & 31;
    const int row  = blockIdx.x * ROWS_PER_BLOCK + warp;

    const float4* wrow = reinterpret_cast<const float4*>(W + (size_t)row * (2 * H));

    float a0 = 0.f, a1 = 0.f, a2 = 0.f, a3 = 0.f;
    #pragma unroll 8
    for (int i = lane; i < (2 * H) / 4; i += 32) {
        float4 w = wrow[i];
        float4 x = xsv[i];
        a0 = fmaf(w.x, x.x, a0);
        a1 = fmaf(w.y, x.y, a1);
        a2 = fmaf(w.z, x.z, a2);
        a3 = fmaf(w.w, x.w, a3);
    }
    float s = (a0 + a1) + (a2 + a3);
    #pragma unroll
    for (int off = 16; off > 0; off >>= 1)
        s += __shfl_down_sync(0xffffffffu, s, off);

    if (lane == 0) {
        g_z[row]  = s;
        rs[warp]  = s;
        rq[warp]  = s * s;
    }
    __syncthreads();

    // One thread aggregates the block's 8 rows; 2 atomics per block.
    if (tid == 0) {
        float bs = 0.f, bq = 0.f;
        #pragma unroll
        for (int w = 0; w < 8; w++) { bs += rs[w]; bq += rq[w]; }
        const int part = blockIdx.x >> 9;     // 512 blocks per part
        atomicAdd(&g_sum[part],   bs);
        atomicAdd(&g_sumsq[part], bq);
    }
}

// ---------------------------------------------------------------------------
// Kernel 2: epilogue. One CTA, 1024 threads; thread t owns float4 index t of
// every 4096-wide vector. Part stats are already accumulated by kernel 1.
// ---------------------------------------------------------------------------
__global__ __launch_bounds__(1024, 1)
void epilogue_kernel(const float* __restrict__ c0,
                     const float* __restrict__ c1,
                     const float* __restrict__ ffio_g,
                     const float* __restrict__ ffio_b,
                     const float* __restrict__ u_g,
                     const float* __restrict__ u_b,
                     const float* __restrict__ c_g,
                     const float* __restrict__ c_b,
                     float* __restrict__ out)
{
    const int t    = threadIdx.x;   // 0..1023 = float4 index
    const int warp = t >> 5;
    const int lane = t & 31;

    __shared__ float red_s[32];
    __shared__ float red_q[32];
    __shared__ float stat_mc;       // cell mean
    __shared__ float stat_rc;       // cell rstd

    // Per-thread read of precomputed part statistics (L2-resident, broadcast).
    float m5[5], r5[5];
    #pragma unroll
    for (int p = 0; p < 5; p++) {
        float s = g_sum[p];
        float q = g_sumsq[p];
        float mean = s * (1.0f / H);
        float var  = q * (1.0f / H) - mean * mean;
        m5[p] = mean;
        r5[p] = rsqrtf(var + EPS);
    }

    const float4* gz4 = reinterpret_cast<const float4*>(g_z);

    // Load z parts
    float v[5][4];
    #pragma unroll
    for (int p = 0; p < 5; p++) {
        float4 vv = gz4[p * (H / 4) + t];
        v[p][0] = vv.x; v[p][1] = vv.y; v[p][2] = vv.z; v[p][3] = vv.w;
    }

    // Gates (sigmoid(LN)) and u (tanh(LN))
    float gate[4][4];
    #pragma unroll
    for (int p = 0; p < 4; p++) {
        float4 gv = reinterpret_cast<const float4*>(ffio_g + p * H)[t];
        float4 bv = reinterpret_cast<const float4*>(ffio_b + p * H)[t];
        float ga[4] = {gv.x, gv.y, gv.z, gv.w};
        float ba[4] = {bv.x, bv.y, bv.z, bv.w};
        float m = m5[p], r = r5[p];
        #pragma unroll
        for (int k = 0; k < 4; k++)
            gate[p][k] = sigmoidf_(fmaf((v[p][k] - m) * r, ga[k], ba[k]));
    }

    float uval[4];
    {
        float4 gv = reinterpret_cast<const float4*>(u_g)[t];
        float4 bv = reinterpret_cast<const float4*>(u_b)[t];
        float m = m5[4], r = r5[4];
        uval[0] = tanhf_(fmaf((v[4][0] - m) * r, gv.x, bv.x));
        uval[1] = tanhf_(fmaf((v[4][1] - m) * r, gv.y, bv.y));
        uval[2] = tanhf_(fmaf((v[4][2] - m) * r, gv.z, bv.z));
        uval[3] = tanhf_(fmaf((v[4][3] - m) * r, gv.w, bv.w));
    }

    float4 c0v = reinterpret_cast<const float4*>(c0)[t];
    float4 c1v = reinterpret_cast<const float4*>(c1)[t];
    float c0a[4] = {c0v.x, c0v.y, c0v.z, c0v.w};
    float c1a[4] = {c1v.x, c1v.y, c1v.z, c1v.w};

    float cell[4];
    #pragma unroll
    for (int k = 0; k < 4; k++)
        cell[k] = fmaf(gate[2][k], uval[k],
                  fmaf(gate[0][k], c0a[k], gate[1][k] * c1a[k]));

    // Block-wide reduction for cell LN
    {
        float s = (cell[0] + cell[1]) + (cell[2] + cell[3]);
        float q = fmaf(cell[0], cell[0], fmaf(cell[1], cell[1],
                  fmaf(cell[2], cell[2], cell[3] * cell[3])));
        #pragma unroll
        for (int off = 16; off > 0; off >>= 1) {
            s += __shfl_down_sync(0xffffffffu, s, off);
            q += __shfl_down_sync(0xffffffffu, q, off);
        }
        if (lane == 0) { red_s[warp] = s; red_q[warp] = q; }
    }
    __syncthreads();

    // All threads have consumed g_sum/g_sumsq; reset for next graph replay.
    if (t >= 64 && t < 69)  g_sum[t - 64]   = 0.f;
    if (t >= 96 && t < 101) g_sumsq[t - 96] = 0.f;

    if (warp == 0) {
        float s = red_s[lane];
        float q = red_q[lane];
        #pragma unroll
        for (int off = 16; off > 0; off >>= 1) {
            s += __shfl_down_sync(0xffffffffu, s, off);
            q += __shfl_down_sync(0xffffffffu, q, off);
        }
        if (lane == 0) {
            float mean = s * (1.0f / H);
            float var  = q * (1.0f / H) - mean * mean;
            stat_mc = mean;
            stat_rc = rsqrtf(var + EPS);
        }
    }
    __syncthreads();

    // Final LN on cell + outputs
    const float m = stat_mc, r = stat_rc;
    float4 cgv = reinterpret_cast<const float4*>(c_g)[t];
    float4 cbv = reinterpret_cast<const float4*>(c_b)[t];
    float cga[4] = {cgv.x, cgv.y, cgv.z, cgv.w};
    float cba[4] = {cbv.x, cbv.y, cbv.z, cbv.w};

    float4 hid, ncl;
    float nc[4], hd[4];
    #pragma unroll
    for (int k = 0; k < 4; k++) {
        nc[k] = fmaf((cell[k] - m) * r, cga[k], cba[k]);
        hd[k] = gate[3][k] * tanhf_(nc[k]);
    }
    hid.x = hd[0]; hid.y = hd[1]; hid.z = hd[2]; hid.w = hd[3];
    ncl.x = nc[0]; ncl.y = nc[1]; ncl.z = nc[2]; ncl.w = nc[3];

    reinterpret_cast<float4*>(out)[t]     = hid;   // new_hidden
    reinterpret_cast<float4*>(out + H)[t] = ncl;   // new_cell
}

// ---------------------------------------------------------------------------
// Inputs (metadata order): 0=h0, 1=c0, 2=h1, 3=c1, 4=W,
//   5=ffio_g(4H), 6=ffio_b(4H), 7=u_g, 8=u_b, 9=c_g, 10=c_b
// Output: [new_hidden(4096); new_cell(4096)] fp32
// ---------------------------------------------------------------------------
extern "C" void kernel_launch(void* const* d_in, const int* in_sizes, int n_in,
                              void* d_out, int out_size)
{
    const float* h0     = (const float*)d_in[0];
    const float* c0     = (const float*)d_in[1];
    const float* h1     = (const float*)d_in[2];
    const float* c1     = (const float*)d_in[3];
    const float* W      = (const float*)d_in[4];
    const float* ffio_g = (const float*)d_in[5];
    const float* ffio_b = (const float*)d_in[6];
    const float* u_g    = (const float*)d_in[7];
    const float* u_b    = (const float*)d_in[8];
    const float* c_g    = (const float*)d_in[9];
    const float* c_b    = (const float*)d_in[10];
    float* out = (float*)d_out;

    gemv_kernel<<<NBLOCKS, 256>>>(h0, h1, W);
    epilogue_kernel<<<1, 1024>>>(c0, c1, ffio_g, ffio_b, u_g, u_b, c_g, c_b, out);
}

// round 5
// speedup vs baseline: 1.1345x; 1.0026x over previous
#include <cuda_runtime.h>
#include <math.h>

#define H 4096
#define EPS 1e-5f
#define ROWS_PER_BLOCK 8
#define NBLOCKS (5 * H / ROWS_PER_BLOCK)   // 2560, 512 blocks per z-part
#define EBLOCKS 16
#define ETHR 64                             // 16*64 = 1024 float4 = H/4

// Scratch + accumulators (no device allocation allowed).
__device__ float g_z[5 * H];
__device__ float g_sum[5]   = {0.f, 0.f, 0.f, 0.f, 0.f};
__device__ float g_sumsq[5] = {0.f, 0.f, 0.f, 0.f, 0.f};
__device__ float g_csum   = 0.f;
__device__ float g_csumsq = 0.f;
__device__ unsigned int g_cnt  = 0;
__device__ unsigned int g_done = 0;

__device__ __forceinline__ float sigmoidf_(float x) {
    return 1.0f / (1.0f + __expf(-x));
}
// tanh(x) = 1 - 2/(exp(2x)+1); saturates correctly at +/-inf.
__device__ __forceinline__ float tanhf_(float x) {
    return 1.0f - 2.0f / (__expf(2.0f * x) + 1.0f);
}

// ---------------------------------------------------------------------------
// Kernel 1: GEMV  z[r] = dot(W[r, 0:2H], [h0;h1]) ; one warp per row.
// W read with __ldcs (evict-first streaming) so it does not own L2 —
// epilogue inputs (z, ffio params, c0/c1) stay L2-resident.
// Also accumulates per-part (sum, sumsq) of z via 2 atomicAdds per block.
// ---------------------------------------------------------------------------
__global__ __launch_bounds__(256, 4)
void gemv_kernel(const float* __restrict__ h0,
                 const float* __restrict__ h1,
                 const float* __restrict__ W)
{
    __shared__ float xs[2 * H];
    __shared__ float rs[8], rq[8];

    const int tid = threadIdx.x;

    const float4* h0v = reinterpret_cast<const float4*>(h0);
    const float4* h1v = reinterpret_cast<const float4*>(h1);
    float4* xsv = reinterpret_cast<float4*>(xs);
    #pragma unroll
    for (int i = tid; i < H / 4; i += 256) {
        xsv[i]         = h0v[i];
        xsv[i + H / 4] = h1v[i];
    }
    __syncthreads();

    const int warp = tid >> 5;
    const int lane = tid & 31;
    const int row  = blockIdx.x * ROWS_PER_BLOCK + warp;

    const float4* wrow = reinterpret_cast<const float4*>(W + (size_t)row * (2 * H));

    float a0 = 0.f, a1 = 0.f, a2 = 0.f, a3 = 0.f;
    #pragma unroll 8
    for (int i = lane; i < (2 * H) / 4; i += 32) {
        float4 w = __ldcs(&wrow[i]);
        float4 x = xsv[i];
        a0 = fmaf(w.x, x.x, a0);
        a1 = fmaf(w.y, x.y, a1);
        a2 = fmaf(w.z, x.z, a2);
        a3 = fmaf(w.w, x.w, a3);
    }
    float s = (a0 + a1) + (a2 + a3);
    #pragma unroll
    for (int off = 16; off > 0; off >>= 1)
        s += __shfl_down_sync(0xffffffffu, s, off);

    if (lane == 0) {
        g_z[row] = s;
        rs[warp] = s;
        rq[warp] = s * s;
    }
    __syncthreads();

    if (tid == 0) {
        float bs = 0.f, bq = 0.f;
        #pragma unroll
        for (int w = 0; w < 8; w++) { bs += rs[w]; bq += rq[w]; }
        const int part = blockIdx.x >> 9;     // 512 blocks per part
        atomicAdd(&g_sum[part],   bs);
        atomicAdd(&g_sumsq[part], bq);
    }
}

// ---------------------------------------------------------------------------
// Kernel 2: epilogue, 16 CTAs x 64 threads; thread owns one float4 column
// g = blockIdx*64 + tid of every 4096-wide vector. Cross-CTA cell-LN stats
// via 2 float atomics + a 16-block counter spin (cell/o stay in registers).
// ---------------------------------------------------------------------------
__global__ __launch_bounds__(ETHR, 1)
void epilogue_kernel(const float* __restrict__ c0,
                     const float* __restrict__ c1,
                     const float* __restrict__ ffio_g,
                     const float* __restrict__ ffio_b,
                     const float* __restrict__ u_g,
                     const float* __restrict__ u_b,
                     const float* __restrict__ c_g,
                     const float* __restrict__ c_b,
                     float* __restrict__ out)
{
    const int t    = threadIdx.x;   // 0..63
    const int warp = t >> 5;
    const int lane = t & 31;
    const int g    = blockIdx.x * ETHR + t;   // float4 index 0..1023

    __shared__ float red_s[2], red_q[2];
    __shared__ float s_mc, s_rc;

    // Part statistics (written by kernel 1; visible across launch boundary).
    float m5[5], r5[5];
    #pragma unroll
    for (int p = 0; p < 5; p++) {
        float mean = g_sum[p] * (1.0f / H);
        float var  = g_sumsq[p] * (1.0f / H) - mean * mean;
        m5[p] = mean;
        r5[p] = rsqrtf(var + EPS);
    }

    const float4* gz4 = reinterpret_cast<const float4*>(g_z);

    float v[5][4];
    #pragma unroll
    for (int p = 0; p < 5; p++) {
        float4 vv = gz4[p * (H / 4) + g];
        v[p][0] = vv.x; v[p][1] = vv.y; v[p][2] = vv.z; v[p][3] = vv.w;
    }

    float gate[4][4];
    #pragma unroll
    for (int p = 0; p < 4; p++) {
        float4 gv = reinterpret_cast<const float4*>(ffio_g + p * H)[g];
        float4 bv = reinterpret_cast<const float4*>(ffio_b + p * H)[g];
        float ga[4] = {gv.x, gv.y, gv.z, gv.w};
        float ba[4] = {bv.x, bv.y, bv.z, bv.w};
        float m = m5[p], r = r5[p];
        #pragma unroll
        for (int k = 0; k < 4; k++)
            gate[p][k] = sigmoidf_(fmaf((v[p][k] - m) * r, ga[k], ba[k]));
    }

    float uval[4];
    {
        float4 gv = reinterpret_cast<const float4*>(u_g)[g];
        float4 bv = reinterpret_cast<const float4*>(u_b)[g];
        float m = m5[4], r = r5[4];
        uval[0] = tanhf_(fmaf((v[4][0] - m) * r, gv.x, bv.x));
        uval[1] = tanhf_(fmaf((v[4][1] - m) * r, gv.y, bv.y));
        uval[2] = tanhf_(fmaf((v[4][2] - m) * r, gv.z, bv.z));
        uval[3] = tanhf_(fmaf((v[4][3] - m) * r, gv.w, bv.w));
    }

    float4 c0v = reinterpret_cast<const float4*>(c0)[g];
    float4 c1v = reinterpret_cast<const float4*>(c1)[g];
    float c0a[4] = {c0v.x, c0v.y, c0v.z, c0v.w};
    float c1a[4] = {c1v.x, c1v.y, c1v.z, c1v.w};

    float cell[4];
    #pragma unroll
    for (int k = 0; k < 4; k++)
        cell[k] = fmaf(gate[2][k], uval[k],
                  fmaf(gate[0][k], c0a[k], gate[1][k] * c1a[k]));

    // Block partial (sum, sumsq) of cell
    {
        float s = (cell[0] + cell[1]) + (cell[2] + cell[3]);
        float q = fmaf(cell[0], cell[0], fmaf(cell[1], cell[1],
                  fmaf(cell[2], cell[2], cell[3] * cell[3])));
        #pragma unroll
        for (int off = 16; off > 0; off >>= 1) {
            s += __shfl_down_sync(0xffffffffu, s, off);
            q += __shfl_down_sync(0xffffffffu, q, off);
        }
        if (lane == 0) { red_s[warp] = s; red_q[warp] = q; }
    }
    __syncthreads();

    // Thread 0: publish partials, arrive, spin until all 16 blocks arrived.
    if (t == 0) {
        atomicAdd(&g_csum,   red_s[0] + red_s[1]);
        atomicAdd(&g_csumsq, red_q[0] + red_q[1]);
        __threadfence();
        atomicAdd(&g_cnt, 1u);
        while (*((volatile unsigned int*)&g_cnt) < EBLOCKS)
            __nanosleep(32);
        __threadfence();
        float cs = atomicAdd(&g_csum,   0.0f);
        float cq = atomicAdd(&g_csumsq, 0.0f);
        float mean = cs * (1.0f / H);
        float var  = cq * (1.0f / H) - mean * mean;
        s_mc = mean;
        s_rc = rsqrtf(var + EPS);
    }
    __syncthreads();

    // Final LN on cell + outputs
    const float m = s_mc, r = s_rc;
    float4 cgv = reinterpret_cast<const float4*>(c_g)[g];
    float4 cbv = reinterpret_cast<const float4*>(c_b)[g];
    float cga[4] = {cgv.x, cgv.y, cgv.z, cgv.w};
    float cba[4] = {cbv.x, cbv.y, cbv.z, cbv.w};

    float4 hid, ncl;
    float nc[4], hd[4];
    #pragma unroll
    for (int k = 0; k < 4; k++) {
        nc[k] = fmaf((cell[k] - m) * r, cga[k], cba[k]);
        hd[k] = gate[3][k] * tanhf_(nc[k]);
    }
    hid.x = hd[0]; hid.y = hd[1]; hid.z = hd[2]; hid.w = hd[3];
    ncl.x = nc[0]; ncl.y = nc[1]; ncl.z = nc[2]; ncl.w = nc[3];

    reinterpret_cast<float4*>(out)[g]     = hid;   // new_hidden
    reinterpret_cast<float4*>(out + H)[g] = ncl;   // new_cell

    // Last block to finish resets all cross-launch state for graph replay.
    __syncthreads();
    if (t == 0) {
        unsigned int prev = atomicAdd(&g_done, 1u);
        if (prev == EBLOCKS - 1) {
            g_cnt = 0; g_done = 0;
            g_csum = 0.f; g_csumsq = 0.f;
            #pragma unroll
            for (int p = 0; p < 5; p++) { g_sum[p] = 0.f; g_sumsq[p] = 0.f; }
        }
    }
}

// ---------------------------------------------------------------------------
// Inputs (metadata order): 0=h0, 1=c0, 2=h1, 3=c1, 4=W,
//   5=ffio_g(4H), 6=ffio_b(4H), 7=u_g, 8=u_b, 9=c_g, 10=c_b
// Output: [new_hidden(4096); new_cell(4096)] fp32
// ---------------------------------------------------------------------------
extern "C" void kernel_launch(void* const* d_in, const int* in_sizes, int n_in,
                              void* d_out, int out_size)
{
    const float* h0     = (const float*)d_in[0];
    const float* c0     = (const float*)d_in[1];
    const float* h1     = (const float*)d_in[2];
    const float* c1     = (const float*)d_in[3];
    const float* W      = (const float*)d_in[4];
    const float* ffio_g = (const float*)d_in[5];
    const float* ffio_b = (const float*)d_in[6];
    const float* u_g    = (const float*)d_in[7];
    const float* u_b    = (const float*)d_in[8];
    const float* c_g    = (const float*)d_in[9];
    const float* c_b    = (const float*)d_in[10];
    float* out = (float*)d_out;

    gemv_kernel<<<NBLOCKS, 256>>>(h0, h1, W);
    epilogue_kernel<<<EBLOCKS, ETHR>>>(c0, c1, ffio_g, ffio_b,
                                       u_g, u_b, c_g, c_b, out);
}